// round 16
// baseline (speedup 1.0000x reference)
#include <cuda_runtime.h>
#include <cuda_bf16.h>
#include <cuda_fp16.h>
#include <math.h>
#include <stdint.h>

#define N_NODES 50000
#define N_EDGES 800000
#define E_TOT   (N_EDGES + N_NODES)
#define IN_C    128
#define HID_C   32
#define OUT_C   64
#define HEADS   8
#define HC1     (HEADS * HID_C)   // 256
#define SCAN_B  1024
#define N_SCAN_BLOCKS ((N_NODES + SCAN_B - 1) / SCAN_B)   // 49
#define M1PAD   50048   // 391 * 128
#define M2PAD   50176   // 196 * 256

// ---------------- static scratch ----------------
__device__ __align__(16) uint32_t g_xs[(long)M1PAD * IN_C];
__device__ __align__(16) uint32_t g_w1s[4 * 8 * 64 * 16];
__device__ __align__(16) uint32_t g_w2s[1 * 16 * 64 * 16];
__device__ __align__(16) uint32_t g_out1s[(long)M2PAD * HC1];
__device__ __align__(16) __half g_h1h[N_NODES * HC1];
__device__ __align__(16) __half g_h2h[N_NODES * OUT_C];
__device__ float g_es1[N_NODES * HEADS];
__device__ float g_ed1[N_NODES * HEADS];
__device__ float g_es2[N_NODES];
__device__ float g_ed2[N_NODES];
__device__ int   g_indptr[N_NODES + 1];
__device__ int   g_cursor[N_NODES];
__device__ int   g_deg[N_NODES];
__device__ int   g_local[N_NODES];
__device__ int   g_bsum[N_SCAN_BLOCKS];
__device__ int   g_srcs[E_TOT];

__device__ __forceinline__ void mma_bf16(float* c, const uint32_t* a, const uint32_t* b) {
    asm volatile(
        "mma.sync.aligned.m16n8k16.row.col.f32.bf16.bf16.f32 "
        "{%0,%1,%2,%3}, {%4,%5,%6,%7}, {%8,%9}, {%0,%1,%2,%3};"
        : "+f"(c[0]), "+f"(c[1]), "+f"(c[2]), "+f"(c[3])
        : "r"(a[0]), "r"(a[1]), "r"(a[2]), "r"(a[3]), "r"(b[0]), "r"(b[1]));
}
__device__ __forceinline__ void split2(float x0, float x1, uint32_t& hi, uint32_t& lo) {
    __nv_bfloat162 h = __floats2bfloat162_rn(x0, x1);
    float r0 = x0 - __bfloat162float(h.x);
    float r1 = x1 - __bfloat162float(h.y);
    __nv_bfloat162 l = __floats2bfloat162_rn(r0, r1);
    hi = *reinterpret_cast<uint32_t*>(&h);
    lo = *reinterpret_cast<uint32_t*>(&l);
}
__device__ __forceinline__ void cp16(void* sdst, const void* gsrc) {
    uint32_t sa = (uint32_t)__cvta_generic_to_shared(sdst);
    asm volatile("cp.async.cg.shared.global [%0], [%1], 16;" :: "r"(sa), "l"(gsrc));
}

// ---------------- pre-split kernels ----------------
__global__ void split_a_kernel(const float* __restrict__ A, uint32_t* __restrict__ out,
                               int M, int K) {
    int KT = K / 16;
    long j = (long)blockIdx.x * blockDim.x + threadIdx.x;
    if (j >= (long)M * KT) return;
    int r = (int)(j / KT), kt = (int)(j % KT);
    const float4* src = (const float4*)(A + (long)r * K + kt * 16);
    uint32_t hi[8], lo[8];
    #pragma unroll
    for (int q = 0; q < 4; q++) {
        float4 v = src[q];
        split2(v.x, v.y, hi[q * 2], lo[q * 2]);
        split2(v.z, v.w, hi[q * 2 + 1], lo[q * 2 + 1]);
    }
    uint32_t* dst = out + (long)r * K + kt * 16;
    *(uint4*)(dst)      = *(uint4*)&hi[0];
    *(uint4*)(dst + 4)  = *(uint4*)&hi[4];
    *(uint4*)(dst + 8)  = *(uint4*)&lo[0];
    *(uint4*)(dst + 12) = *(uint4*)&lo[4];
}
__global__ void split_w_kernel(const float* __restrict__ W, uint32_t* __restrict__ out,
                               int K, int N) {
    int KT = K / 16;
    int total = (N / 64) * KT * 64;
    int j = blockIdx.x * blockDim.x + threadIdx.x;
    if (j >= total) return;
    int nl = j & 63;
    int kt = (j >> 6) % KT;
    int nb = j / (64 * KT);
    int n = nb * 64 + nl;
    int swl = (nl >> 3) & 3;
    __nv_bfloat16 buf[32];
    #pragma unroll
    for (int k = 0; k < 16; k++) {
        float x = W[(long)(kt * 16 + k) * N + n];
        __nv_bfloat16 hb = __float2bfloat16(x);
        float r = x - __bfloat162float(hb);
        __nv_bfloat16 lb = __float2bfloat16(r);
        int pos = (((k >> 1) ^ swl) << 1) + (k & 1);
        buf[pos] = hb;
        buf[16 + pos] = lb;
    }
    uint4* d4 = (uint4*)(out + ((long)(nb * KT + kt) * 64 + nl) * 16);
    uint4* s4 = (uint4*)buf;
    d4[0] = s4[0]; d4[1] = s4[1]; d4[2] = s4[2]; d4[3] = s4[3];
}

// ---------------- split-BF16 tensor GEMM + fp16-out + fused attention scores ------
// MODE 1: persistent grid-stride over 128x128 tiles, warps 4x2, 2-stage cp.async.
// MODE 2: block 256x64, warps 8x1, single buffer.
#define AP 20
#define STG_PITCH 72

template <int MODE>
__global__ __launch_bounds__(256, 2) void bf16_gemm_attn_kernel(
        const uint32_t* __restrict__ Ap, const uint32_t* __restrict__ Bp,
        __half* __restrict__ C, int M, int N, int K,
        const float* __restrict__ a_src, const float* __restrict__ a_dst,
        float* __restrict__ es, float* __restrict__ ed, int numTiles) {
    constexpr int MT = (MODE == 1) ? 128 : 256;
    constexpr int NT = (MODE == 1) ? 128 : 64;
    constexpr int NBUF = (MODE == 1) ? 2 : 1;
    constexpr int TILE_U32 = (MT + NT) * AP;
    constexpr int FILL_BYTES  = NBUF * TILE_U32 * 4;
    constexpr int STAGE_BYTES = 8 * 32 * STG_PITCH * 2;
    constexpr int SMEM_BYTES  = FILL_BYTES > STAGE_BYTES ? FILL_BYTES : STAGE_BYTES;
    __shared__ __align__(16) unsigned char smem_raw[SMEM_BYTES];

    int tid = threadIdx.x;
    int wid = tid >> 5, lane = tid & 31;
    int warp_row = (MODE == 1) ? (wid & 3) : wid;
    int warp_col = (MODE == 1) ? (wid >> 2) : 0;
    int g = lane >> 2, t = lane & 3;
    const int KT = K / 16;

    for (int tile = blockIdx.x; tile < numTiles; tile += gridDim.x) {
        int rowBase, colBase;
        if (MODE == 1) {
            rowBase = (tile >> 1) * MT;
            colBase = (tile & 1) * NT;
        } else {
            rowBase = tile * MT;
            colBase = 0;
        }

        float acc[2][8][4] = {};

        if (MODE == 1) {
            auto bufA = [&](int b) { return (uint32_t*)smem_raw + b * TILE_U32; };
            auto bufB = [&](int b) { return (uint32_t*)smem_raw + b * TILE_U32 + MT * AP; };
            int ar = tid >> 1, ahf = tid & 1;
            int bn = tid >> 2, bq = tid & 3;
            auto issue_tile = [&](int kt, int b) {
                uint32_t* Asb = bufA(b);
                uint32_t* Bsb = bufB(b);
                const uint32_t* srcA = Ap + (long)(rowBase + ar) * K + kt * 16 + ahf * 8;
                cp16(&Asb[ar * AP + ahf * 8], srcA);
                cp16(&Asb[ar * AP + ahf * 8 + 4], srcA + 4);
                #pragma unroll
                for (int l = 0; l < 2; l++) {
                    int nb = (colBase >> 6) + l;
                    const uint32_t* srcB = Bp + ((long)(nb * KT + kt) * 64 + bn) * 16 + bq * 4;
                    cp16(&Bsb[(l * 64 + bn) * AP + bq * 4], srcB);
                }
                asm volatile("cp.async.commit_group;");
            };
            issue_tile(0, 0);
            for (int kt = 0; kt < KT; kt++) {
                int cur = kt & 1;
                if (kt + 1 < KT) {
                    issue_tile(kt + 1, cur ^ 1);
                    asm volatile("cp.async.wait_group 1;");
                } else {
                    asm volatile("cp.async.wait_group 0;");
                }
                __syncthreads();
                uint32_t (*As)[AP] = (uint32_t(*)[AP])bufA(cur);
                uint32_t (*Bs)[AP] = (uint32_t(*)[AP])bufB(cur);
                #pragma unroll
                for (int p = 0; p < 3; p++) {
                    int sA = (p == 1) ? 8 : 0;
                    int sB = (p == 2) ? 8 : 0;
                    uint32_t bf[8][2];
                    #pragma unroll
                    for (int nt = 0; nt < 8; nt++) {
                        int cb = warp_col * 64 + nt * 8 + g;
                        int tw = t ^ (nt & 3);
                        bf[nt][0] = Bs[cb][sB + tw];
                        bf[nt][1] = Bs[cb][sB + tw + 4];
                    }
                    #pragma unroll
                    for (int mt = 0; mt < 2; mt++) {
                        int ra = warp_row * 32 + mt * 16 + g;
                        uint32_t af[4];
                        af[0] = As[ra][sA + t];
                        af[1] = As[ra + 8][sA + t];
                        af[2] = As[ra][sA + t + 4];
                        af[3] = As[ra + 8][sA + t + 4];
                        #pragma unroll
                        for (int nt = 0; nt < 8; nt++)
                            mma_bf16(acc[mt][nt], af, bf[nt]);
                    }
                }
                __syncthreads();
            }
        } else {
            uint32_t (*As)[AP] = (uint32_t(*)[AP])smem_raw;
            uint32_t (*Bs)[AP] = (uint32_t(*)[AP])(smem_raw + MT * AP * 4);
            for (int kt = 0; kt < KT; kt++) {
                #pragma unroll
                for (int l = 0; l < MT / 128; l++) {
                    int r = (tid >> 1) + l * 128;
                    int hf = tid & 1;
                    const uint32_t* src = Ap + (long)(rowBase + r) * K + kt * 16 + hf * 8;
                    *(uint4*)&As[r][hf * 8]     = *(const uint4*)src;
                    *(uint4*)&As[r][hf * 8 + 4] = *(const uint4*)(src + 4);
                }
                {
                    int nb = (colBase >> 6);
                    const uint32_t* src = Bp + ((long)(nb * KT + kt) * 64) * 16;
                    int n = tid >> 2, q = tid & 3;
                    *(uint4*)&Bs[n][q * 4] = *(const uint4*)(src + n * 16 + q * 4);
                }
                __syncthreads();
                #pragma unroll
                for (int p = 0; p < 3; p++) {
                    int sA = (p == 1) ? 8 : 0;
                    int sB = (p == 2) ? 8 : 0;
                    uint32_t bf[8][2];
                    #pragma unroll
                    for (int nt = 0; nt < 8; nt++) {
                        int cb = warp_col * 64 + nt * 8 + g;
                        int tw = t ^ (nt & 3);
                        bf[nt][0] = Bs[cb][sB + tw];
                        bf[nt][1] = Bs[cb][sB + tw + 4];
                    }
                    #pragma unroll
                    for (int mt = 0; mt < 2; mt++) {
                        int ra = warp_row * 32 + mt * 16 + g;
                        uint32_t af[4];
                        af[0] = As[ra][sA + t];
                        af[1] = As[ra + 8][sA + t];
                        af[2] = As[ra][sA + t + 4];
                        af[3] = As[ra + 8][sA + t + 4];
                        #pragma unroll
                        for (int nt = 0; nt < 8; nt++)
                            mma_bf16(acc[mt][nt], af, bf[nt]);
                    }
                }
                __syncthreads();
            }
        }

        // ---- fused attention-score dots ----
        if (MODE == 1) {
            #pragma unroll
            for (int grp = 0; grp < 2; grp++) {
                int head = (colBase + warp_col * 64 + grp * 32) >> 5;
                float av0[4], av1[4], dv0[4], dv1[4];
                #pragma unroll
                for (int q = 0; q < 4; q++) {
                    int cih = q * 8 + 2 * t;
                    av0[q] = a_src[head * 32 + cih];
                    av1[q] = a_src[head * 32 + cih + 1];
                    dv0[q] = a_dst[head * 32 + cih];
                    dv1[q] = a_dst[head * 32 + cih + 1];
                }
                #pragma unroll
                for (int mt = 0; mt < 2; mt++) {
                    #pragma unroll
                    for (int half = 0; half < 2; half++) {
                        float pe = 0.f, pd = 0.f;
                        #pragma unroll
                        for (int q = 0; q < 4; q++) {
                            int nt = grp * 4 + q;
                            pe += acc[mt][nt][half * 2] * av0[q] + acc[mt][nt][half * 2 + 1] * av1[q];
                            pd += acc[mt][nt][half * 2] * dv0[q] + acc[mt][nt][half * 2 + 1] * dv1[q];
                        }
                        pe += __shfl_xor_sync(0xffffffffu, pe, 1);
                        pe += __shfl_xor_sync(0xffffffffu, pe, 2);
                        pd += __shfl_xor_sync(0xffffffffu, pd, 1);
                        pd += __shfl_xor_sync(0xffffffffu, pd, 2);
                        int gr = rowBase + warp_row * 32 + mt * 16 + half * 8 + g;
                        if (t == 0 && gr < M) {
                            es[gr * 8 + head] = pe;
                            ed[gr * 8 + head] = pd;
                        }
                    }
                }
            }
        } else {
            float av0[8], av1[8], dv0[8], dv1[8];
            #pragma unroll
            for (int nt = 0; nt < 8; nt++) {
                int c = colBase + nt * 8 + 2 * t;
                av0[nt] = a_src[c];
                av1[nt] = a_src[c + 1];
                dv0[nt] = a_dst[c];
                dv1[nt] = a_dst[c + 1];
            }
            #pragma unroll
            for (int mt = 0; mt < 2; mt++) {
                #pragma unroll
                for (int half = 0; half < 2; half++) {
                    float pe = 0.f, pd = 0.f;
                    #pragma unroll
                    for (int nt = 0; nt < 8; nt++) {
                        pe += acc[mt][nt][half * 2] * av0[nt] + acc[mt][nt][half * 2 + 1] * av1[nt];
                        pd += acc[mt][nt][half * 2] * dv0[nt] + acc[mt][nt][half * 2 + 1] * dv1[nt];
                    }
                    pe += __shfl_xor_sync(0xffffffffu, pe, 1);
                    pe += __shfl_xor_sync(0xffffffffu, pe, 2);
                    pd += __shfl_xor_sync(0xffffffffu, pd, 1);
                    pd += __shfl_xor_sync(0xffffffffu, pd, 2);
                    int gr = rowBase + warp_row * 32 + mt * 16 + half * 8 + g;
                    if (t == 0 && gr < M) {
                        es[gr] = pe;
                        ed[gr] = pd;
                    }
                }
            }
        }

        // ---- C store fp16 via per-warp smem staging ----
        __syncthreads();   // tile-buffer reads done before staging aliases them
        __half (*st)[STG_PITCH] = (__half(*)[STG_PITCH])(smem_raw + wid * 32 * STG_PITCH * 2);
        #pragma unroll
        for (int mt = 0; mt < 2; mt++) {
            #pragma unroll
            for (int half = 0; half < 2; half++) {
                int lr = mt * 16 + half * 8 + g;
                #pragma unroll
                for (int nt = 0; nt < 8; nt++)
                    *(__half2*)&st[lr][nt * 8 + 2 * t] =
                        __floats2half2_rn(acc[mt][nt][half * 2], acc[mt][nt][half * 2 + 1]);
            }
        }
        __syncwarp();
        #pragma unroll
        for (int it = 0; it < 8; it++) {
            int lr = it * 4 + (lane >> 3);
            int c = lane & 7;
            int gr = rowBase + warp_row * 32 + lr;
            if (gr < M) {
                uint4 v = *(uint4*)&st[lr][c * 8];
                *(uint4*)(C + (long)gr * N + colBase + warp_col * 64 + c * 8) = v;
            }
        }
        __syncthreads();   // staging reads done before next tile's fills
    }
}

// ---------------- CSR build ----------------
__global__ void fill0_kernel(int* p, int n) {
    int i = blockIdx.x * blockDim.x + threadIdx.x;
    if (i < n) p[i] = 0;
}
__global__ void count_deg_kernel(const int* __restrict__ ei, int* deg) {
    int e = blockIdx.x * blockDim.x + threadIdx.x;
    if (e >= E_TOT) return;
    int d = (e < N_EDGES) ? ei[N_EDGES + e] : e - N_EDGES;
    atomicAdd(&deg[d], 1);
}
__global__ __launch_bounds__(SCAN_B) void scan_p1(const int* __restrict__ deg,
                                                  int* __restrict__ local,
                                                  int* __restrict__ bsum, int n) {
    __shared__ int wsum[32];
    int tid = threadIdx.x;
    int i = blockIdx.x * SCAN_B + tid;
    int lane = tid & 31, wid = tid >> 5;
    int v = (i < n) ? deg[i] : 0;
    int incl = v;
    #pragma unroll
    for (int off = 1; off < 32; off <<= 1) {
        int t = __shfl_up_sync(0xffffffffu, incl, off);
        if (lane >= off) incl += t;
    }
    if (lane == 31) wsum[wid] = incl;
    __syncthreads();
    if (wid == 0) {
        int wv = wsum[lane];
        int wincl = wv;
        #pragma unroll
        for (int off = 1; off < 32; off <<= 1) {
            int t = __shfl_up_sync(0xffffffffu, wincl, off);
            if (lane >= off) wincl += t;
        }
        wsum[lane] = wincl - wv;
        if (lane == 31) bsum[blockIdx.x] = wincl;
    }
    __syncthreads();
    if (i < n) local[i] = incl - v + wsum[wid];
}
__global__ void scan_p2(int* __restrict__ bsum, int* __restrict__ indptr_end, int nb) {
    int lane = threadIdx.x;
    int carry = 0;
    for (int base = 0; base < nb; base += 32) {
        int idx = base + lane;
        int v = (idx < nb) ? bsum[idx] : 0;
        int incl = v;
        #pragma unroll
        for (int off = 1; off < 32; off <<= 1) {
            int t = __shfl_up_sync(0xffffffffu, incl, off);
            if (lane >= off) incl += t;
        }
        if (idx < nb) bsum[idx] = incl - v + carry;
        carry += __shfl_sync(0xffffffffu, incl, 31);
    }
    if (lane == 0) *indptr_end = carry;
}
__global__ void scan_p3(const int* __restrict__ local, const int* __restrict__ bsum,
                        int* __restrict__ indptr, int* __restrict__ cursor, int n) {
    int i = blockIdx.x * blockDim.x + threadIdx.x;
    if (i >= n) return;
    int v = local[i] + bsum[i >> 10];
    indptr[i] = v;
    cursor[i] = v;
}
__global__ void scatter_kernel(const int* __restrict__ ei, int* cursor, int* srcs) {
    int e = blockIdx.x * blockDim.x + threadIdx.x;
    if (e >= E_TOT) return;
    int s, d;
    if (e < N_EDGES) { s = ei[e]; d = ei[N_EDGES + e]; }
    else             { s = d = e - N_EDGES; }
    int pos = atomicAdd(&cursor[d], 1);
    srcs[pos] = s;
}

// ---------------- fused layer-1 gather: warp per node, 8 heads, fp16 in, split out --
__global__ void gat_gather8_kernel(const int* __restrict__ indptr,
                                   const int* __restrict__ srcs,
                                   const float* __restrict__ es,
                                   const float* __restrict__ ed,
                                   const __half* __restrict__ hfeat,
                                   const float* __restrict__ bias,
                                   uint32_t* __restrict__ outs) {
    int n = (int)((blockIdx.x * blockDim.x + threadIdx.x) >> 5);
    int lane = threadIdx.x & 31;
    if (n >= N_NODES) return;
    int beg = indptr[n], end = indptr[n + 1];
    int g = lane >> 3;
    int h = lane & 7;
    float edv = ed[n * 8 + h];

    float m = -INFINITY, ssum = 0.f;
    for (int i = beg + g; i < end; i += 4) {
        int s = srcs[i];
        float v = es[s * 8 + h] + edv;
        v = v > 0.f ? v : 0.2f * v;
        float nm = fmaxf(m, v);
        ssum = ssum * __expf(m - nm) + __expf(v - nm);
        m = nm;
    }
    #pragma unroll
    for (int off = 8; off <= 16; off <<= 1) {
        float om = __shfl_xor_sync(0xffffffffu, m, off);
        float os = __shfl_xor_sync(0xffffffffu, ssum, off);
        float nm = fmaxf(m, om);
        float sa = (m  == -INFINITY) ? 0.f : __expf(m  - nm);
        float sb = (om == -INFINITY) ? 0.f : __expf(om - nm);
        ssum = ssum * sa + os * sb;
        m = nm;
    }
    float inv_den = 1.f / (ssum + 1e-16f);

    int myhead = lane >> 2;
    float acc[8] = {};
    int nfull = (end - beg) & ~3;
    int i0 = beg;
    for (; i0 < beg + nfull; i0 += 4) {
        int s = srcs[i0 + g];
        float v = es[s * 8 + h] + edv;
        v = v > 0.f ? v : 0.2f * v;
        float a = __expf(v - m) * inv_den;
        #pragma unroll
        for (int j = 0; j < 4; j++) {
            int   sj = __shfl_sync(0xffffffffu, s, j * 8);
            float aj = __shfl_sync(0xffffffffu, a, j * 8 + myhead);
            uint4 rv = ((const uint4*)(hfeat + (long)sj * 256))[lane];
            const __half2* hp = (const __half2*)&rv;
            float2 f0 = __half22float2(hp[0]);
            float2 f1 = __half22float2(hp[1]);
            float2 f2 = __half22float2(hp[2]);
            float2 f3 = __half22float2(hp[3]);
            acc[0] += aj * f0.x; acc[1] += aj * f0.y;
            acc[2] += aj * f1.x; acc[3] += aj * f1.y;
            acc[4] += aj * f2.x; acc[5] += aj * f2.y;
            acc[6] += aj * f3.x; acc[7] += aj * f3.y;
        }
    }
    if (i0 < end) {
        float a = 0.f; int s = 0;
        int i = i0 + g;
        if (i < end) {
            s = srcs[i];
            float v = es[s * 8 + h] + edv;
            v = v > 0.f ? v : 0.2f * v;
            a = __expf(v - m) * inv_den;
        }
        int cnt = end - i0;
        for (int j = 0; j < cnt; j++) {
            int   sj = __shfl_sync(0xffffffffu, s, j * 8);
            float aj = __shfl_sync(0xffffffffu, a, j * 8 + myhead);
            uint4 rv = ((const uint4*)(hfeat + (long)sj * 256))[lane];
            const __half2* hp = (const __half2*)&rv;
            float2 f0 = __half22float2(hp[0]);
            float2 f1 = __half22float2(hp[1]);
            float2 f2 = __half22float2(hp[2]);
            float2 f3 = __half22float2(hp[3]);
            acc[0] += aj * f0.x; acc[1] += aj * f0.y;
            acc[2] += aj * f1.x; acc[3] += aj * f1.y;
            acc[4] += aj * f2.x; acc[5] += aj * f2.y;
            acc[6] += aj * f3.x; acc[7] += aj * f3.y;
        }
    }

    float bv[8];
    *(float4*)&bv[0] = *(const float4*)(bias + 8 * lane);
    *(float4*)&bv[4] = *(const float4*)(bias + 8 * lane + 4);
    float o[8];
    #pragma unroll
    for (int k = 0; k < 8; k++) {
        float v = acc[k] + bv[k];
        o[k] = v > 0.f ? v : expm1f(v);
    }
    uint32_t hiw[4], low[4];
    split2(o[0], o[1], hiw[0], low[0]);
    split2(o[2], o[3], hiw[1], low[1]);
    split2(o[4], o[5], hiw[2], low[2]);
    split2(o[6], o[7], hiw[3], low[3]);
    uint32_t* orow = outs + (long)n * 256 + (lane >> 1) * 16 + (lane & 1) * 4;
    *(uint4*)orow       = *(uint4*)hiw;
    *(uint4*)(orow + 8) = *(uint4*)low;
}

// ---------------- layer-2 gather ----------------
__global__ void gat_gather1_kernel(const int* __restrict__ indptr,
                                   const int* __restrict__ srcs,
                                   const float* __restrict__ es,
                                   const float* __restrict__ ed,
                                   const __half* __restrict__ hfeat,
                                   const float* __restrict__ bias,
                                   float* __restrict__ out) {
    int n = (int)((blockIdx.x * blockDim.x + threadIdx.x) >> 5);
    int lane = threadIdx.x & 31;
    if (n >= N_NODES) return;
    int beg = indptr[n], end = indptr[n + 1];
    float edv = ed[n];

    float m = -INFINITY, ssum = 0.f;
    for (int i = beg + lane; i < end; i += 32) {
        int s = srcs[i];
        float v = es[s] + edv;
        v = v > 0.f ? v : 0.2f * v;
        float nm = fmaxf(m, v);
        ssum = ssum * __expf(m - nm) + __expf(v - nm);
        m = nm;
    }
    #pragma unroll
    for (int off = 16; off; off >>= 1) {
        float om = __shfl_xor_sync(0xffffffffu, m, off);
        float os = __shfl_xor_sync(0xffffffffu, ssum, off);
        float nm = fmaxf(m, om);
        float sa = (m  == -INFINITY) ? 0.f : __expf(m  - nm);
        float sb = (om == -INFINITY) ? 0.f : __expf(om - nm);
        ssum = ssum * sa + os * sb;
        m = nm;
    }
    float inv_den = 1.f / (ssum + 1e-16f);

    float acc0 = 0.f, acc1 = 0.f;
    int nfull = (end - beg) & ~31;
    int i0 = beg;
    for (; i0 < beg + nfull; i0 += 32) {
        int s = srcs[i0 + lane];
        float v = es[s] + edv;
        v = v > 0.f ? v : 0.2f * v;
        float alpha = __expf(v - m) * inv_den;
        #pragma unroll 8
        for (int j = 0; j < 32; j++) {
            float a  = __shfl_sync(0xffffffffu, alpha, j);
            int   sj = __shfl_sync(0xffffffffu, s, j);
            float2 f = __half22float2(((const __half2*)(hfeat + (long)sj * 64))[lane]);
            acc0 += a * f.x;
            acc1 += a * f.y;
        }
    }
    if (i0 < end) {
        int i = i0 + lane;
        float alpha = 0.f; int s = 0;
        if (i < end) {
            s = srcs[i];
            float v = es[s] + edv;
            v = v > 0.f ? v : 0.2f * v;
            alpha = __expf(v - m) * inv_den;
        }
        int cnt = end - i0;
        for (int j = 0; j < cnt; j++) {
            float a  = __shfl_sync(0xffffffffu, alpha, j);
            int   sj = __shfl_sync(0xffffffffu, s, j);
            float2 f = __half22float2(((const __half2*)(hfeat + (long)sj * 64))[lane]);
            acc0 += a * f.x;
            acc1 += a * f.y;
        }
    }
    out[(long)n * 64 + 2 * lane]     = acc0 + bias[2 * lane];
    out[(long)n * 64 + 2 * lane + 1] = acc1 + bias[2 * lane + 1];
}

static inline long cdivl(long a, long b) { return (a + b - 1) / b; }

extern "C" void kernel_launch(void* const* d_in, const int* in_sizes, int n_in,
                              void* d_out, int out_size) {
    const float* x      = (const float*)d_in[0];
    const int*   ei     = (const int*)d_in[1];
    const float* W1     = (const float*)d_in[2];
    const float* a_src1 = (const float*)d_in[3];
    const float* a_dst1 = (const float*)d_in[4];
    const float* b1     = (const float*)d_in[5];
    const float* W2     = (const float*)d_in[6];
    const float* a_src2 = (const float*)d_in[7];
    const float* a_dst2 = (const float*)d_in[8];
    const float* b2     = (const float*)d_in[9];
    float* out = (float*)d_out;

    uint32_t *xs, *w1s, *w2s, *out1s;
    __half *h1h, *h2h;
    float *es1, *ed1, *es2, *ed2;
    int *indptr, *cursor, *deg, *local, *bsum, *srcs;
    cudaGetSymbolAddress((void**)&xs,     g_xs);
    cudaGetSymbolAddress((void**)&w1s,    g_w1s);
    cudaGetSymbolAddress((void**)&w2s,    g_w2s);
    cudaGetSymbolAddress((void**)&out1s,  g_out1s);
    cudaGetSymbolAddress((void**)&h1h,    g_h1h);
    cudaGetSymbolAddress((void**)&h2h,    g_h2h);
    cudaGetSymbolAddress((void**)&es1,    g_es1);
    cudaGetSymbolAddress((void**)&ed1,    g_ed1);
    cudaGetSymbolAddress((void**)&es2,    g_es2);
    cudaGetSymbolAddress((void**)&ed2,    g_ed2);
    cudaGetSymbolAddress((void**)&indptr, g_indptr);
    cudaGetSymbolAddress((void**)&cursor, g_cursor);
    cudaGetSymbolAddress((void**)&deg,    g_deg);
    cudaGetSymbolAddress((void**)&local,  g_local);
    cudaGetSymbolAddress((void**)&bsum,   g_bsum);
    cudaGetSymbolAddress((void**)&srcs,   g_srcs);

    const int T = 256;

    cudaStream_t side;
    cudaStreamCreate(&side);
    cudaEvent_t evFork, evJoin, evW;
    cudaEventCreateWithFlags(&evFork, cudaEventDisableTiming);
    cudaEventCreateWithFlags(&evJoin, cudaEventDisableTiming);
    cudaEventCreateWithFlags(&evW,    cudaEventDisableTiming);
    cudaEventRecord(evFork, 0);
    cudaStreamWaitEvent(side, evFork, 0);

    // ---- side: weight splits + CSR build ----
    split_w_kernel<<<cdivl((HC1 / 64) * (IN_C / 16) * 64, T), T, 0, side>>>(W1, w1s, IN_C, HC1);
    split_w_kernel<<<cdivl((OUT_C / 64) * (HC1 / 16) * 64, T), T, 0, side>>>(W2, w2s, HC1, OUT_C);
    cudaEventRecord(evW, side);
    fill0_kernel<<<cdivl(N_NODES, T), T, 0, side>>>(deg, N_NODES);
    count_deg_kernel<<<cdivl(E_TOT, T), T, 0, side>>>(ei, deg);
    scan_p1<<<N_SCAN_BLOCKS, SCAN_B, 0, side>>>(deg, local, bsum, N_NODES);
    scan_p2<<<1, 32, 0, side>>>(bsum, indptr + N_NODES, N_SCAN_BLOCKS);
    scan_p3<<<cdivl(N_NODES, T), T, 0, side>>>(local, bsum, indptr, cursor, N_NODES);
    scatter_kernel<<<cdivl(E_TOT, T), T, 0, side>>>(ei, cursor, srcs);
    cudaEventRecord(evJoin, side);

    // ---- main: split x, wait for W1 split, persistent layer-1 GEMM ----
    split_a_kernel<<<cdivl((long)N_NODES * (IN_C / 16), T), T>>>(x, xs, N_NODES, IN_C);
    cudaStreamWaitEvent(0, evW, 0);
    {
        int numTiles = 2 * (int)cdivl(N_NODES, 128);   // 782
        int grid = 296;                                 // 2 CTAs/SM x 148 SMs
        bf16_gemm_attn_kernel<1><<<grid, 256>>>(xs, w1s, h1h, N_NODES, HC1, IN_C,
                                                a_src1, a_dst1, es1, ed1, numTiles);
    }

    // ---- main: join CSR, gather, layer 2, gather ----
    cudaStreamWaitEvent(0, evJoin, 0);
    gat_gather8_kernel<<<cdivl((long)N_NODES * 32, T), T>>>(indptr, srcs, es1, ed1, h1h, b1, out1s);
    {
        int numTiles = (int)cdivl(N_NODES, 256);       // 196
        bf16_gemm_attn_kernel<2><<<numTiles, 256>>>(out1s, w2s, h2h, N_NODES, OUT_C, HC1,
                                                    a_src2, a_dst2, es2, ed2, numTiles);
    }
    gat_gather1_kernel<<<cdivl((long)N_NODES * 32, T), T>>>(indptr, srcs, es2, ed2, h2h, b2, out);
    // Handles intentionally not destroyed (graph capture may still reference them).
}

// round 17
// speedup vs baseline: 1.0295x; 1.0295x over previous
#include <cuda_runtime.h>
#include <cuda_bf16.h>
#include <cuda_fp16.h>
#include <math.h>
#include <stdint.h>

#define N_NODES 50000
#define N_EDGES 800000
#define E_TOT   (N_EDGES + N_NODES)
#define IN_C    128
#define HID_C   32
#define OUT_C   64
#define HEADS   8
#define HC1     (HEADS * HID_C)   // 256
#define SCAN_B  1024
#define N_SCAN_BLOCKS ((N_NODES + SCAN_B - 1) / SCAN_B)   // 49
#define M1PAD   50048   // 391 * 128
#define M2PAD   50176   // 196 * 256

// ---------------- static scratch ----------------
__device__ __align__(16) uint32_t g_xs[(long)M1PAD * IN_C];
__device__ __align__(16) uint32_t g_w1s[4 * 8 * 64 * 16];
__device__ __align__(16) uint32_t g_w2s[1 * 16 * 64 * 16];
__device__ __align__(16) uint32_t g_out1s[(long)M2PAD * HC1];
__device__ __align__(16) __half g_h1h[N_NODES * HC1];
__device__ __align__(16) __half g_h2h[N_NODES * OUT_C];
__device__ float g_es1[N_NODES * HEADS];
__device__ float g_ed1[N_NODES * HEADS];
__device__ float g_es2[N_NODES];
__device__ float g_ed2[N_NODES];
__device__ int   g_indptr[N_NODES + 1];
__device__ int   g_cursor[N_NODES];
__device__ int   g_deg[N_NODES];
__device__ int   g_local[N_NODES];
__device__ int   g_bsum[N_SCAN_BLOCKS];
__device__ int   g_srcs[E_TOT];

__device__ __forceinline__ void mma_bf16(float* c, const uint32_t* a, const uint32_t* b) {
    asm volatile(
        "mma.sync.aligned.m16n8k16.row.col.f32.bf16.bf16.f32 "
        "{%0,%1,%2,%3}, {%4,%5,%6,%7}, {%8,%9}, {%0,%1,%2,%3};"
        : "+f"(c[0]), "+f"(c[1]), "+f"(c[2]), "+f"(c[3])
        : "r"(a[0]), "r"(a[1]), "r"(a[2]), "r"(a[3]), "r"(b[0]), "r"(b[1]));
}
__device__ __forceinline__ void split2(float x0, float x1, uint32_t& hi, uint32_t& lo) {
    __nv_bfloat162 h = __floats2bfloat162_rn(x0, x1);
    float r0 = x0 - __bfloat162float(h.x);
    float r1 = x1 - __bfloat162float(h.y);
    __nv_bfloat162 l = __floats2bfloat162_rn(r0, r1);
    hi = *reinterpret_cast<uint32_t*>(&h);
    lo = *reinterpret_cast<uint32_t*>(&l);
}

// ---------------- pre-split kernels ----------------
__global__ void split_a_kernel(const float* __restrict__ A, uint32_t* __restrict__ out,
                               int M, int K) {
    int KT = K / 16;
    long j = (long)blockIdx.x * blockDim.x + threadIdx.x;
    if (j >= (long)M * KT) return;
    int r = (int)(j / KT), kt = (int)(j % KT);
    const float4* src = (const float4*)(A + (long)r * K + kt * 16);
    uint32_t hi[8], lo[8];
    #pragma unroll
    for (int q = 0; q < 4; q++) {
        float4 v = src[q];
        split2(v.x, v.y, hi[q * 2], lo[q * 2]);
        split2(v.z, v.w, hi[q * 2 + 1], lo[q * 2 + 1]);
    }
    uint32_t* dst = out + (long)r * K + kt * 16;
    *(uint4*)(dst)      = *(uint4*)&hi[0];
    *(uint4*)(dst + 4)  = *(uint4*)&hi[4];
    *(uint4*)(dst + 8)  = *(uint4*)&lo[0];
    *(uint4*)(dst + 12) = *(uint4*)&lo[4];
}
__global__ void split_w_kernel(const float* __restrict__ W, uint32_t* __restrict__ out,
                               int K, int N) {
    int KT = K / 16;
    int total = (N / 64) * KT * 64;
    int j = blockIdx.x * blockDim.x + threadIdx.x;
    if (j >= total) return;
    int nl = j & 63;
    int kt = (j >> 6) % KT;
    int nb = j / (64 * KT);
    int n = nb * 64 + nl;
    int swl = (nl >> 3) & 3;
    __nv_bfloat16 buf[32];
    #pragma unroll
    for (int k = 0; k < 16; k++) {
        float x = W[(long)(kt * 16 + k) * N + n];
        __nv_bfloat16 hb = __float2bfloat16(x);
        float r = x - __bfloat162float(hb);
        __nv_bfloat16 lb = __float2bfloat16(r);
        int pos = (((k >> 1) ^ swl) << 1) + (k & 1);
        buf[pos] = hb;
        buf[16 + pos] = lb;
    }
    uint4* d4 = (uint4*)(out + ((long)(nb * KT + kt) * 64 + nl) * 16);
    uint4* s4 = (uint4*)buf;
    d4[0] = s4[0]; d4[1] = s4[1]; d4[2] = s4[2]; d4[3] = s4[3];
}

// ---------------- split-BF16 tensor GEMM + fp16-out + fused attention scores ------
// MODE 1: block 128x128, warps 4x2; heads of 32 cols -> es/ed [M,8]
// MODE 2: block 256x64,  warps 8x1; single head      -> es/ed [M]
#define AP 20
#define STG_PITCH 72

template <int MODE>
__global__ __launch_bounds__(256, 2) void bf16_gemm_attn_kernel(
        const uint32_t* __restrict__ Ap, const uint32_t* __restrict__ Bp,
        __half* __restrict__ C, int M, int N, int K,
        const float* __restrict__ a_src, const float* __restrict__ a_dst,
        float* __restrict__ es, float* __restrict__ ed) {
    constexpr int MT = (MODE == 1) ? 128 : 256;
    constexpr int NT = (MODE == 1) ? 128 : 64;
    constexpr int FILL_BYTES  = (MT + NT) * AP * 4;
    constexpr int STAGE_BYTES = 8 * 32 * STG_PITCH * 2;
    constexpr int SMEM_BYTES  = FILL_BYTES > STAGE_BYTES ? FILL_BYTES : STAGE_BYTES;
    __shared__ __align__(16) unsigned char smem_raw[SMEM_BYTES];
    uint32_t (*As)[AP] = (uint32_t(*)[AP])smem_raw;
    uint32_t (*Bs)[AP] = (uint32_t(*)[AP])(smem_raw + MT * AP * 4);

    int tid = threadIdx.x;
    int wid = tid >> 5, lane = tid & 31;
    int warp_row = (MODE == 1) ? (wid & 3) : wid;
    int warp_col = (MODE == 1) ? (wid >> 2) : 0;
    int g = lane >> 2, t = lane & 3;
    int rowBase = blockIdx.y * MT;
    int colBase = blockIdx.x * NT;

    float acc[2][8][4] = {};
    const int KT = K / 16;

    for (int kt = 0; kt < KT; kt++) {
        #pragma unroll
        for (int l = 0; l < MT / 128; l++) {
            int r = (tid >> 1) + l * 128;
            int hf = tid & 1;
            const uint32_t* src = Ap + (long)(rowBase + r) * K + kt * 16 + hf * 8;
            *(uint4*)&As[r][hf * 8]     = *(const uint4*)src;
            *(uint4*)&As[r][hf * 8 + 4] = *(const uint4*)(src + 4);
        }
        #pragma unroll
        for (int l = 0; l < NT / 64; l++) {
            int nb = (colBase >> 6) + l;
            const uint32_t* src = Bp + ((long)(nb * KT + kt) * 64) * 16;
            int n = tid >> 2, q = tid & 3;
            *(uint4*)&Bs[l * 64 + n][q * 4] = *(const uint4*)(src + n * 16 + q * 4);
        }
        __syncthreads();

        #pragma unroll
        for (int p = 0; p < 3; p++) {
            int sA = (p == 1) ? 8 : 0;
            int sB = (p == 2) ? 8 : 0;
            uint32_t bf[8][2];
            #pragma unroll
            for (int nt = 0; nt < 8; nt++) {
                int cb = warp_col * 64 + nt * 8 + g;
                int tw = t ^ (nt & 3);
                bf[nt][0] = Bs[cb][sB + tw];
                bf[nt][1] = Bs[cb][sB + tw + 4];
            }
            #pragma unroll
            for (int mt = 0; mt < 2; mt++) {
                int ra = warp_row * 32 + mt * 16 + g;
                uint32_t af[4];
                af[0] = As[ra][sA + t];
                af[1] = As[ra + 8][sA + t];
                af[2] = As[ra][sA + t + 4];
                af[3] = As[ra + 8][sA + t + 4];
                #pragma unroll
                for (int nt = 0; nt < 8; nt++)
                    mma_bf16(acc[mt][nt], af, bf[nt]);
            }
        }
        __syncthreads();
    }

    // ---- fused attention-score dots ----
    if (MODE == 1) {
        #pragma unroll
        for (int grp = 0; grp < 2; grp++) {
            int head = (colBase + warp_col * 64 + grp * 32) >> 5;
            float av0[4], av1[4], dv0[4], dv1[4];
            #pragma unroll
            for (int q = 0; q < 4; q++) {
                int cih = q * 8 + 2 * t;
                av0[q] = a_src[head * 32 + cih];
                av1[q] = a_src[head * 32 + cih + 1];
                dv0[q] = a_dst[head * 32 + cih];
                dv1[q] = a_dst[head * 32 + cih + 1];
            }
            #pragma unroll
            for (int mt = 0; mt < 2; mt++) {
                #pragma unroll
                for (int half = 0; half < 2; half++) {
                    float pe = 0.f, pd = 0.f;
                    #pragma unroll
                    for (int q = 0; q < 4; q++) {
                        int nt = grp * 4 + q;
                        pe += acc[mt][nt][half * 2] * av0[q] + acc[mt][nt][half * 2 + 1] * av1[q];
                        pd += acc[mt][nt][half * 2] * dv0[q] + acc[mt][nt][half * 2 + 1] * dv1[q];
                    }
                    pe += __shfl_xor_sync(0xffffffffu, pe, 1);
                    pe += __shfl_xor_sync(0xffffffffu, pe, 2);
                    pd += __shfl_xor_sync(0xffffffffu, pd, 1);
                    pd += __shfl_xor_sync(0xffffffffu, pd, 2);
                    int gr = rowBase + warp_row * 32 + mt * 16 + half * 8 + g;
                    if (t == 0 && gr < M) {
                        es[gr * 8 + head] = pe;
                        ed[gr * 8 + head] = pd;
                    }
                }
            }
        }
    } else {
        float av0[8], av1[8], dv0[8], dv1[8];
        #pragma unroll
        for (int nt = 0; nt < 8; nt++) {
            int c = colBase + nt * 8 + 2 * t;
            av0[nt] = a_src[c];
            av1[nt] = a_src[c + 1];
            dv0[nt] = a_dst[c];
            dv1[nt] = a_dst[c + 1];
        }
        #pragma unroll
        for (int mt = 0; mt < 2; mt++) {
            #pragma unroll
            for (int half = 0; half < 2; half++) {
                float pe = 0.f, pd = 0.f;
                #pragma unroll
                for (int nt = 0; nt < 8; nt++) {
                    pe += acc[mt][nt][half * 2] * av0[nt] + acc[mt][nt][half * 2 + 1] * av1[nt];
                    pd += acc[mt][nt][half * 2] * dv0[nt] + acc[mt][nt][half * 2 + 1] * dv1[nt];
                }
                pe += __shfl_xor_sync(0xffffffffu, pe, 1);
                pe += __shfl_xor_sync(0xffffffffu, pe, 2);
                pd += __shfl_xor_sync(0xffffffffu, pd, 1);
                pd += __shfl_xor_sync(0xffffffffu, pd, 2);
                int gr = rowBase + warp_row * 32 + mt * 16 + half * 8 + g;
                if (t == 0 && gr < M) {
                    es[gr] = pe;
                    ed[gr] = pd;
                }
            }
        }
    }

    // ---- C store fp16 via per-warp smem staging ----
    __syncthreads();
    __half (*st)[STG_PITCH] = (__half(*)[STG_PITCH])(smem_raw + wid * 32 * STG_PITCH * 2);
    #pragma unroll
    for (int mt = 0; mt < 2; mt++) {
        #pragma unroll
        for (int half = 0; half < 2; half++) {
            int lr = mt * 16 + half * 8 + g;
            #pragma unroll
            for (int nt = 0; nt < 8; nt++)
                *(__half2*)&st[lr][nt * 8 + 2 * t] =
                    __floats2half2_rn(acc[mt][nt][half * 2], acc[mt][nt][half * 2 + 1]);
        }
    }
    __syncwarp();
    #pragma unroll
    for (int it = 0; it < 8; it++) {
        int lr = it * 4 + (lane >> 3);
        int c = lane & 7;
        int gr = rowBase + warp_row * 32 + lr;
        if (gr < M) {
            uint4 v = *(uint4*)&st[lr][c * 8];
            *(uint4*)(C + (long)gr * N + colBase + warp_col * 64 + c * 8) = v;
        }
    }
}

// ---------------- CSR build ----------------
__global__ void fill0_kernel(int* p, int n) {
    int i = blockIdx.x * blockDim.x + threadIdx.x;
    if (i < n) p[i] = 0;
}
__global__ void count_deg_kernel(const int* __restrict__ ei, int* deg) {
    int e = blockIdx.x * blockDim.x + threadIdx.x;
    if (e >= E_TOT) return;
    int d = (e < N_EDGES) ? ei[N_EDGES + e] : e - N_EDGES;
    atomicAdd(&deg[d], 1);
}
__global__ __launch_bounds__(SCAN_B) void scan_p1(const int* __restrict__ deg,
                                                  int* __restrict__ local,
                                                  int* __restrict__ bsum, int n) {
    __shared__ int wsum[32];
    int tid = threadIdx.x;
    int i = blockIdx.x * SCAN_B + tid;
    int lane = tid & 31, wid = tid >> 5;
    int v = (i < n) ? deg[i] : 0;
    int incl = v;
    #pragma unroll
    for (int off = 1; off < 32; off <<= 1) {
        int t = __shfl_up_sync(0xffffffffu, incl, off);
        if (lane >= off) incl += t;
    }
    if (lane == 31) wsum[wid] = incl;
    __syncthreads();
    if (wid == 0) {
        int wv = wsum[lane];
        int wincl = wv;
        #pragma unroll
        for (int off = 1; off < 32; off <<= 1) {
            int t = __shfl_up_sync(0xffffffffu, wincl, off);
            if (lane >= off) wincl += t;
        }
        wsum[lane] = wincl - wv;
        if (lane == 31) bsum[blockIdx.x] = wincl;
    }
    __syncthreads();
    if (i < n) local[i] = incl - v + wsum[wid];
}
__global__ void scan_p2(int* __restrict__ bsum, int* __restrict__ indptr_end, int nb) {
    int lane = threadIdx.x;
    int carry = 0;
    for (int base = 0; base < nb; base += 32) {
        int idx = base + lane;
        int v = (idx < nb) ? bsum[idx] : 0;
        int incl = v;
        #pragma unroll
        for (int off = 1; off < 32; off <<= 1) {
            int t = __shfl_up_sync(0xffffffffu, incl, off);
            if (lane >= off) incl += t;
        }
        if (idx < nb) bsum[idx] = incl - v + carry;
        carry += __shfl_sync(0xffffffffu, incl, 31);
    }
    if (lane == 0) *indptr_end = carry;
}
__global__ void scan_p3(const int* __restrict__ local, const int* __restrict__ bsum,
                        int* __restrict__ indptr, int* __restrict__ cursor, int n) {
    int i = blockIdx.x * blockDim.x + threadIdx.x;
    if (i >= n) return;
    int v = local[i] + bsum[i >> 10];
    indptr[i] = v;
    cursor[i] = v;
}
__global__ void scatter_kernel(const int* __restrict__ ei, int* cursor, int* srcs) {
    int e = blockIdx.x * blockDim.x + threadIdx.x;
    if (e >= E_TOT) return;
    int s, d;
    if (e < N_EDGES) { s = ei[e]; d = ei[N_EDGES + e]; }
    else             { s = d = e - N_EDGES; }
    int pos = atomicAdd(&cursor[d], 1);
    srcs[pos] = s;
}

// ---------------- layer-1 gather: SINGLE-PASS online softmax aggregation ----------
// warp per node, 8 heads; lane owns channels [8*lane, 8*lane+8), head = lane>>2.
// The 4 lanes of a head run identical (m, ssum) updates -> no cross-lane merge.
__global__ void gat_gather8_kernel(const int* __restrict__ indptr,
                                   const int* __restrict__ srcs,
                                   const float* __restrict__ es,
                                   const float* __restrict__ ed,
                                   const __half* __restrict__ hfeat,
                                   const float* __restrict__ bias,
                                   uint32_t* __restrict__ outs) {
    int n = (int)((blockIdx.x * blockDim.x + threadIdx.x) >> 5);
    int lane = threadIdx.x & 31;
    if (n >= N_NODES) return;
    int beg = indptr[n], end = indptr[n + 1];
    int g = lane >> 3;        // edge slot 0..3 (score computation)
    int h = lane & 7;         // head        (score computation)
    int myhead = lane >> 2;   // head owning this lane's channels
    float edv = ed[n * 8 + h];

    float m = -INFINITY, ssum = 0.f;
    float acc[8] = {};
    for (int i0 = beg; i0 < end; i0 += 4) {
        int i = i0 + g;
        float v = -INFINITY;
        int s = 0;
        if (i < end) {
            s = srcs[i];
            float vv = es[s * 8 + h] + edv;
            v = vv > 0.f ? vv : 0.2f * vv;
        }
        #pragma unroll
        for (int j = 0; j < 4; j++) {
            int   sj = __shfl_sync(0xffffffffu, s, j * 8);
            float vj = __shfl_sync(0xffffffffu, v, j * 8 + myhead);
            float nm = fmaxf(m, vj);
            float sc = __expf(m - nm);    // first valid edge: m=-inf -> sc=0
            float e  = __expf(vj - nm);   // invalid edge: vj=-inf -> e=0
            m = nm;
            ssum = ssum * sc + e;
            uint4 rv = ((const uint4*)(hfeat + (long)sj * 256))[lane];
            const __half2* hp = (const __half2*)&rv;
            float2 f0 = __half22float2(hp[0]);
            float2 f1 = __half22float2(hp[1]);
            float2 f2 = __half22float2(hp[2]);
            float2 f3 = __half22float2(hp[3]);
            acc[0] = acc[0] * sc + e * f0.x; acc[1] = acc[1] * sc + e * f0.y;
            acc[2] = acc[2] * sc + e * f1.x; acc[3] = acc[3] * sc + e * f1.y;
            acc[4] = acc[4] * sc + e * f2.x; acc[5] = acc[5] * sc + e * f2.y;
            acc[6] = acc[6] * sc + e * f3.x; acc[7] = acc[7] * sc + e * f3.y;
        }
    }
    float inv_den = 1.f / (ssum + 1e-16f);

    // epilogue: normalize + bias + ELU, write split-packed (GEMM2-ready)
    float bv[8];
    *(float4*)&bv[0] = *(const float4*)(bias + 8 * lane);
    *(float4*)&bv[4] = *(const float4*)(bias + 8 * lane + 4);
    float o[8];
    #pragma unroll
    for (int k = 0; k < 8; k++) {
        float v = acc[k] * inv_den + bv[k];
        o[k] = v > 0.f ? v : expm1f(v);
    }
    uint32_t hiw[4], low[4];
    split2(o[0], o[1], hiw[0], low[0]);
    split2(o[2], o[3], hiw[1], low[1]);
    split2(o[4], o[5], hiw[2], low[2]);
    split2(o[6], o[7], hiw[3], low[3]);
    uint32_t* orow = outs + (long)n * 256 + (lane >> 1) * 16 + (lane & 1) * 4;
    *(uint4*)orow       = *(uint4*)hiw;
    *(uint4*)(orow + 8) = *(uint4*)low;
}

// ---------------- layer-2 gather: warp per node, H=1, C=64, fp16 features ----------
__global__ void gat_gather1_kernel(const int* __restrict__ indptr,
                                   const int* __restrict__ srcs,
                                   const float* __restrict__ es,
                                   const float* __restrict__ ed,
                                   const __half* __restrict__ hfeat,
                                   const float* __restrict__ bias,
                                   float* __restrict__ out) {
    int n = (int)((blockIdx.x * blockDim.x + threadIdx.x) >> 5);
    int lane = threadIdx.x & 31;
    if (n >= N_NODES) return;
    int beg = indptr[n], end = indptr[n + 1];
    float edv = ed[n];

    float m = -INFINITY, ssum = 0.f;
    for (int i = beg + lane; i < end; i += 32) {
        int s = srcs[i];
        float v = es[s] + edv;
        v = v > 0.f ? v : 0.2f * v;
        float nm = fmaxf(m, v);
        ssum = ssum * __expf(m - nm) + __expf(v - nm);
        m = nm;
    }
    #pragma unroll
    for (int off = 16; off; off >>= 1) {
        float om = __shfl_xor_sync(0xffffffffu, m, off);
        float os = __shfl_xor_sync(0xffffffffu, ssum, off);
        float nm = fmaxf(m, om);
        float sa = (m  == -INFINITY) ? 0.f : __expf(m  - nm);
        float sb = (om == -INFINITY) ? 0.f : __expf(om - nm);
        ssum = ssum * sa + os * sb;
        m = nm;
    }
    float inv_den = 1.f / (ssum + 1e-16f);

    float acc0 = 0.f, acc1 = 0.f;
    int nfull = (end - beg) & ~31;
    int i0 = beg;
    for (; i0 < beg + nfull; i0 += 32) {
        int s = srcs[i0 + lane];
        float v = es[s] + edv;
        v = v > 0.f ? v : 0.2f * v;
        float alpha = __expf(v - m) * inv_den;
        #pragma unroll 8
        for (int j = 0; j < 32; j++) {
            float a  = __shfl_sync(0xffffffffu, alpha, j);
            int   sj = __shfl_sync(0xffffffffu, s, j);
            float2 f = __half22float2(((const __half2*)(hfeat + (long)sj * 64))[lane]);
            acc0 += a * f.x;
            acc1 += a * f.y;
        }
    }
    if (i0 < end) {
        int i = i0 + lane;
        float alpha = 0.f; int s = 0;
        if (i < end) {
            s = srcs[i];
            float v = es[s] + edv;
            v = v > 0.f ? v : 0.2f * v;
            alpha = __expf(v - m) * inv_den;
        }
        int cnt = end - i0;
        for (int j = 0; j < cnt; j++) {
            float a  = __shfl_sync(0xffffffffu, alpha, j);
            int   sj = __shfl_sync(0xffffffffu, s, j);
            float2 f = __half22float2(((const __half2*)(hfeat + (long)sj * 64))[lane]);
            acc0 += a * f.x;
            acc1 += a * f.y;
        }
    }
    out[(long)n * 64 + 2 * lane]     = acc0 + bias[2 * lane];
    out[(long)n * 64 + 2 * lane + 1] = acc1 + bias[2 * lane + 1];
}

static inline long cdivl(long a, long b) { return (a + b - 1) / b; }

extern "C" void kernel_launch(void* const* d_in, const int* in_sizes, int n_in,
                              void* d_out, int out_size) {
    const float* x      = (const float*)d_in[0];
    const int*   ei     = (const int*)d_in[1];
    const float* W1     = (const float*)d_in[2];
    const float* a_src1 = (const float*)d_in[3];
    const float* a_dst1 = (const float*)d_in[4];
    const float* b1     = (const float*)d_in[5];
    const float* W2     = (const float*)d_in[6];
    const float* a_src2 = (const float*)d_in[7];
    const float* a_dst2 = (const float*)d_in[8];
    const float* b2     = (const float*)d_in[9];
    float* out = (float*)d_out;

    uint32_t *xs, *w1s, *w2s, *out1s;
    __half *h1h, *h2h;
    float *es1, *ed1, *es2, *ed2;
    int *indptr, *cursor, *deg, *local, *bsum, *srcs;
    cudaGetSymbolAddress((void**)&xs,     g_xs);
    cudaGetSymbolAddress((void**)&w1s,    g_w1s);
    cudaGetSymbolAddress((void**)&w2s,    g_w2s);
    cudaGetSymbolAddress((void**)&out1s,  g_out1s);
    cudaGetSymbolAddress((void**)&h1h,    g_h1h);
    cudaGetSymbolAddress((void**)&h2h,    g_h2h);
    cudaGetSymbolAddress((void**)&es1,    g_es1);
    cudaGetSymbolAddress((void**)&ed1,    g_ed1);
    cudaGetSymbolAddress((void**)&es2,    g_es2);
    cudaGetSymbolAddress((void**)&ed2,    g_ed2);
    cudaGetSymbolAddress((void**)&indptr, g_indptr);
    cudaGetSymbolAddress((void**)&cursor, g_cursor);
    cudaGetSymbolAddress((void**)&deg,    g_deg);
    cudaGetSymbolAddress((void**)&local,  g_local);
    cudaGetSymbolAddress((void**)&bsum,   g_bsum);
    cudaGetSymbolAddress((void**)&srcs,   g_srcs);

    const int T = 256;

    cudaStream_t side;
    cudaStreamCreate(&side);
    cudaEvent_t evFork, evJoin, evW;
    cudaEventCreateWithFlags(&evFork, cudaEventDisableTiming);
    cudaEventCreateWithFlags(&evJoin, cudaEventDisableTiming);
    cudaEventCreateWithFlags(&evW,    cudaEventDisableTiming);
    cudaEventRecord(evFork, 0);
    cudaStreamWaitEvent(side, evFork, 0);

    // ---- side: weight splits + CSR build ----
    split_w_kernel<<<cdivl((HC1 / 64) * (IN_C / 16) * 64, T), T, 0, side>>>(W1, w1s, IN_C, HC1);
    split_w_kernel<<<cdivl((OUT_C / 64) * (HC1 / 16) * 64, T), T, 0, side>>>(W2, w2s, HC1, OUT_C);
    cudaEventRecord(evW, side);
    fill0_kernel<<<cdivl(N_NODES, T), T, 0, side>>>(deg, N_NODES);
    count_deg_kernel<<<cdivl(E_TOT, T), T, 0, side>>>(ei, deg);
    scan_p1<<<N_SCAN_BLOCKS, SCAN_B, 0, side>>>(deg, local, bsum, N_NODES);
    scan_p2<<<1, 32, 0, side>>>(bsum, indptr + N_NODES, N_SCAN_BLOCKS);
    scan_p3<<<cdivl(N_NODES, T), T, 0, side>>>(local, bsum, indptr, cursor, N_NODES);
    scatter_kernel<<<cdivl(E_TOT, T), T, 0, side>>>(ei, cursor, srcs);
    cudaEventRecord(evJoin, side);

    // ---- main: split x, wait for W1 split, layer-1 GEMM ----
    split_a_kernel<<<cdivl((long)N_NODES * (IN_C / 16), T), T>>>(x, xs, N_NODES, IN_C);
    cudaStreamWaitEvent(0, evW, 0);
    {
        dim3 grid(HC1 / 128, (unsigned)cdivl(N_NODES, 128));
        bf16_gemm_attn_kernel<1><<<grid, 256>>>(xs, w1s, h1h, N_NODES, HC1, IN_C,
                                                a_src1, a_dst1, es1, ed1);
    }

    // ---- main: join CSR, gather (single-pass), layer 2, gather ----
    cudaStreamWaitEvent(0, evJoin, 0);
    gat_gather8_kernel<<<cdivl((long)N_NODES * 32, T), T>>>(indptr, srcs, es1, ed1, h1h, b1, out1s);
    {
        dim3 grid(1, (unsigned)cdivl(N_NODES, 256));
        bf16_gemm_attn_kernel<2><<<grid, 256>>>(out1s, w2s, h2h, N_NODES, OUT_C, HC1,
                                                a_src2, a_dst2, es2, ed2);
    }
    gat_gather1_kernel<<<cdivl((long)N_NODES * 32, T), T>>>(indptr, srcs, es2, ed2, h2h, b2, out);
    // Handles intentionally not destroyed (graph capture may still reference them).
}